// round 5
// baseline (speedup 1.0000x reference)
#include <cuda_runtime.h>
#include <cstdint>

#define Bg   16
#define Nn   128
#define Mm   (Bg * Nn)     // 2048 nodes
#define Dd   256
#define TRI  ((Dd * (Dd + 1)) / 2)   // 32896
#define TRI4 (TRI / 4)               // 8224

__device__ float    g_s[Mm];       // per-node softmax weight
__device__ uint32_t g_desc[TRI4];  // per-group descriptor: zidx | yidx<<9 | flag<<31

// row start offset: start(i) = i*(513-i)/2
__device__ __forceinline__ int row_start(int i) { return (i * (513 - i)) >> 1; }

// row of flat triu element t (exact after integer fixup)
__device__ __forceinline__ int row_of(int t) {
    int i = (int)(0.5f * (513.0f - sqrtf((float)(263169 - 8 * t))));
    if (row_start(i + 1) <= t) i++;
    if (row_start(i) > t)      i--;
    return i;
}

// ---------------------------------------------------------------------------
// K1: fused (a) linear D->1 + segment softmax  (b) descriptor table build.
// One block per graph, 1024 threads (16*1024 = 16384 threads cover TRI4=8224).
// ---------------------------------------------------------------------------
__global__ __launch_bounds__(1024) void k_attn_softmax(
    const float* __restrict__ x, const float* __restrict__ W,
    const float* __restrict__ b)
{
    int g    = blockIdx.x;
    int tid  = threadIdx.x;
    int warp = tid >> 5;
    int lane = tid & 31;

    __shared__ float simp[Nn];
    __shared__ float red[2];

    // ---- descriptor build: one group per thread ----
    {
        int k4 = g * 1024 + tid;
        if (k4 < TRI4) {
            int k  = 4 * k4;
            int i0 = row_of(k);
            int i3 = row_of(k + 3);
            int j0 = k - row_start(i0) + i0;     // column of first element
            int p  = j0 & 3;
            int q  = j0 >> 2;
            uint32_t d = (uint32_t)(p * 68 + q)         // z image index (<512)
                       | ((uint32_t)i0 << 9)            // y index
                       | ((i0 != i3) ? 0x80000000u : 0u);
            g_desc[k4] = d;
        }
    }

    // ---- attention dot products: warp handles 4 nodes ----
    float wv[8];
#pragma unroll
    for (int u = 0; u < 8; u++) wv[u] = __ldg(&W[lane + 32 * u]);

#pragma unroll
    for (int nn = 0; nn < 4; nn++) {
        int node = warp * 4 + nn;
        const float* xr = x + (size_t)(g * Nn + node) * Dd;
        float acc = 0.f;
#pragma unroll
        for (int u = 0; u < 8; u++) acc = fmaf(xr[lane + 32 * u], wv[u], acc);
#pragma unroll
        for (int o = 16; o; o >>= 1) acc += __shfl_xor_sync(0xffffffffu, acc, o);
        if (lane == 0) simp[node] = acc + b[0];
    }
    __syncthreads();

    if (warp == 0) {
        float v0 = simp[lane], v1 = simp[lane + 32],
              v2 = simp[lane + 64], v3 = simp[lane + 96];
        float mx = fmaxf(fmaxf(v0, v1), fmaxf(v2, v3));
#pragma unroll
        for (int o = 16; o; o >>= 1) mx = fmaxf(mx, __shfl_xor_sync(0xffffffffu, mx, o));
        float sum = expf(v0 - mx) + expf(v1 - mx) + expf(v2 - mx) + expf(v3 - mx);
#pragma unroll
        for (int o = 16; o; o >>= 1) sum += __shfl_xor_sync(0xffffffffu, sum, o);
        if (lane == 0) { red[0] = mx; red[1] = sum; }
    }
    __syncthreads();

    if (tid < Nn)
        g_s[g * Nn + tid] = expf(simp[tid] - red[0]) * (1.0f / red[1]);
}

// ---------------------------------------------------------------------------
// K2: per-node outer-product triu stream. One block per node, 256 threads.
// Hot loop is branchless (predicated store skips row-crossing groups);
// a tiny exact epilogue rewrites the <=255 crossing groups per node.
// ---------------------------------------------------------------------------
__global__ __launch_bounds__(256) void k_sop(
    const float* __restrict__ x, float* __restrict__ out)
{
    int m   = blockIdx.x;
    int tid = threadIdx.x;

    __shared__ float  y[Dd + 4];       // padded: z build reads y[255+3]
    __shared__ float4 z[4 * 68];       // 4 phase-shifted float4 images of y

    float s = __ldg(&g_s[m]);
    y[tid]  = x[(size_t)m * Dd + tid] * s;
    if (tid < 4) y[Dd + tid] = 0.0f;
    __syncthreads();

    {   // build phase images: z[c*68+q] = y[4q+c .. 4q+c+3]
        int c = tid >> 6;              // 0..3
        int q = tid & 63;              // 0..63
        int base = 4 * q + c;
        z[c * 68 + q] = make_float4(y[base], y[base + 1], y[base + 2], y[base + 3]);
    }
    __syncthreads();

    float4* __restrict__ out4 = (float4*)(out + (size_t)m * TRI);

    // ---- hot loop: 1 LDG + 1 LDS.128 + 1 LDS + 4 FMUL + @P STG.128 ----
#pragma unroll 4
    for (int k4 = tid; k4 < TRI4; k4 += 256) {
        uint32_t t = __ldg(&g_desc[k4]);
        float4 w  = z[t & 511u];
        float  yi = y[(t >> 9) & 255u];
        float4 r  = make_float4(yi * w.x, yi * w.y, yi * w.z, yi * w.w);
        if ((int)t >= 0)                       // non-crossing -> predicated store
            __stcs(&out4[k4], r);
    }

    // ---- epilogue: exact recompute of row-crossing groups ----
    // One crossing group per row boundary whose start isn't 4-aligned.
    // (Boundaries i=254,255 map to the same group; identical data, benign.)
    for (int bi = tid; bi < 255; bi += 256) {
        int i  = bi + 1;
        int rs = row_start(i);
        if (rs & 3) {
            int k4 = rs >> 2;
            int kk = 4 * k4;
            int rrow = (i >= 2) ? (i - 2) : 0;   // group can start at most 2 rows back
            float vals[4];
#pragma unroll
            for (int e = 0; e < 4; e++) {
                int k = kk + e;
                while (row_start(rrow + 1) <= k) rrow++;
                int j = k - row_start(rrow) + rrow;
                vals[e] = y[rrow] * y[j];
            }
            __stcs(&out4[k4], make_float4(vals[0], vals[1], vals[2], vals[3]));
        }
    }
}

// ---------------------------------------------------------------------------
extern "C" void kernel_launch(void* const* d_in, const int* in_sizes, int n_in,
                              void* d_out, int out_size)
{
    const float* x = (const float*)d_in[0];
    const float* W = (const float*)d_in[3];
    const float* b = (const float*)d_in[4];
    float* out = (float*)d_out;

    k_attn_softmax<<<Bg, 1024>>>(x, W, b);
    k_sop<<<Mm, 256>>>(x, out);
}